// round 2
// baseline (speedup 1.0000x reference)
#include <cuda_runtime.h>
#include <cuda_bf16.h>
#include <math.h>

// Problem constants
#define D_MODEL 2048
#define D_HEAD  128
#define NHEADS  16
#define CLAT    512      // D_KV_LATENT
#define BATCH   2
#define SEQ     2048
#define BS      (BATCH*SEQ)   // 4096

// Scratch (allocation-free rule: __device__ globals)
__device__ float g_latents[(size_t)BS * CLAT];                 // [b*s, c]       8 MB
__device__ float g_quk[(size_t)NHEADS * D_MODEL * CLAT];       // [h][m][c]     64 MB
__device__ float g_ouv[(size_t)NHEADS * D_MODEL * CLAT];       // [h][m][c]     64 MB
__device__ float g_q[(size_t)NHEADS * BS * CLAT];              // [h][b*s][c]  128 MB
__device__ float g_scores[(size_t)NHEADS * BATCH * SEQ * SEQ]; // [(h,b)][s][t] 512 MB
__device__ float g_ctx[(size_t)NHEADS * BS * CLAT];            // [h][b*s][c]  128 MB

#define BM 128
#define BN 128
#define BK 8

// Generic tiled SGEMM: C[z][M,N] = sum_l A[z,l][M,K] * op(B[z,l])
// A(m,k) = TA ? A[k*lda+m] : A[m*lda+k]
// B(k,n) = TB ? B[n*ldb+k] : B[k*ldb+n]
// causalMode: 0 none; 1 skip tiles strictly above diagonal (scores);
//             2 truncate K loop at end of row tile (ctx: attn==0 for t>s)
template<bool TA, bool TB>
__global__ __launch_bounds__(256) void gemm_k(
    const float* __restrict__ A, const float* __restrict__ B, float* __restrict__ C,
    int M, int N, int K, int lda, int ldb, int ldc,
    size_t sAz, size_t sBz, size_t sCz, int zBmod,
    int L, size_t sAL, size_t sBL, int causalMode)
{
    int bn = blockIdx.x, bm = blockIdx.y, z = blockIdx.z;
    if (causalMode == 1 && bn > bm) return;
    int Kend = K;
    if (causalMode == 2) { int lim = (bm + 1) * BM; if (lim < Kend) Kend = lim; }

    A += (size_t)z * sAz;
    B += (size_t)(z % zBmod) * sBz;
    C += (size_t)z * sCz;

    __shared__ float As[BK][BM];
    __shared__ float Bs[BK][BN];

    int tid = threadIdx.x;
    int tx = tid & 15, ty = tid >> 4;
    int m0 = bm * BM, n0 = bn * BN;

    float acc[8][8];
#pragma unroll
    for (int i = 0; i < 8; i++)
#pragma unroll
        for (int j = 0; j < 8; j++) acc[i][j] = 0.f;

    for (int l = 0; l < L; ++l) {
        const float* Al = A + (size_t)l * sAL;
        const float* Bl = B + (size_t)l * sBL;
        for (int k0 = 0; k0 < Kend; k0 += BK) {
            if (!TA) {
                int row = tid >> 1, kq = (tid & 1) * 4;
                float4 v = *(const float4*)&Al[(size_t)(m0 + row) * lda + k0 + kq];
                As[kq + 0][row] = v.x; As[kq + 1][row] = v.y;
                As[kq + 2][row] = v.z; As[kq + 3][row] = v.w;
            } else {
                int k = tid >> 5, m4 = (tid & 31) * 4;
                *(float4*)&As[k][m4] = *(const float4*)&Al[(size_t)(k0 + k) * lda + m0 + m4];
            }
            if (!TB) {
                int k = tid >> 5, n4 = (tid & 31) * 4;
                *(float4*)&Bs[k][n4] = *(const float4*)&Bl[(size_t)(k0 + k) * ldb + n0 + n4];
            } else {
                int row = tid >> 1, kq = (tid & 1) * 4;
                float4 v = *(const float4*)&Bl[(size_t)(n0 + row) * ldb + k0 + kq];
                Bs[kq + 0][row] = v.x; Bs[kq + 1][row] = v.y;
                Bs[kq + 2][row] = v.z; Bs[kq + 3][row] = v.w;
            }
            __syncthreads();
#pragma unroll
            for (int k = 0; k < BK; k++) {
                float a[8], b[8];
                *(float4*)&a[0] = *(const float4*)&As[k][ty * 4];
                *(float4*)&a[4] = *(const float4*)&As[k][64 + ty * 4];
                *(float4*)&b[0] = *(const float4*)&Bs[k][tx * 4];
                *(float4*)&b[4] = *(const float4*)&Bs[k][64 + tx * 4];
#pragma unroll
                for (int i = 0; i < 8; i++)
#pragma unroll
                    for (int j = 0; j < 8; j++)
                        acc[i][j] = fmaf(a[i], b[j], acc[i][j]);
            }
            __syncthreads();
        }
    }

#pragma unroll
    for (int i = 0; i < 8; i++) {
        int row = m0 + ((i < 4) ? (ty * 4 + i) : (64 + ty * 4 + (i - 4)));
        float4 v0 = make_float4(acc[i][0], acc[i][1], acc[i][2], acc[i][3]);
        float4 v1 = make_float4(acc[i][4], acc[i][5], acc[i][6], acc[i][7]);
        *(float4*)&C[(size_t)row * ldc + n0 + tx * 4] = v0;
        *(float4*)&C[(size_t)row * ldc + n0 + 64 + tx * 4] = v1;
    }
}

// In-place causal softmax over rows of g_scores; zero-fills masked tail so the
// ctx GEMM can read full BK-aligned K ranges.
__global__ __launch_bounds__(256) void softmax_causal_k(float* __restrict__ scores, float scale)
{
    int r = blockIdx.x;                 // 0 .. 32*SEQ-1
    int z = r >> 11;                    // SEQ == 2048
    int s = r & (SEQ - 1);
    float* p = scores + ((size_t)z * SEQ + (size_t)s) * SEQ;
    int n = s + 1;
    int tid = threadIdx.x;
    __shared__ float red[256];

    float m = -3.0e38f;
    for (int j = tid; j < n; j += 256) m = fmaxf(m, p[j]);
    red[tid] = m; __syncthreads();
    for (int o = 128; o > 0; o >>= 1) { if (tid < o) red[tid] = fmaxf(red[tid], red[tid + o]); __syncthreads(); }
    m = red[0]; __syncthreads();

    float sum = 0.f;
    for (int j = tid; j < n; j += 256) {
        float e = expf((p[j] - m) * scale);
        p[j] = e;
        sum += e;
    }
    red[tid] = sum; __syncthreads();
    for (int o = 128; o > 0; o >>= 1) { if (tid < o) red[tid] += red[tid + o]; __syncthreads(); }
    float inv = 1.f / red[0];
    __syncthreads();

    for (int j = tid; j < n; j += 256) p[j] *= inv;
    for (int j = n + tid; j < SEQ; j += 256) p[j] = 0.f;
}

static float* symaddr(const void* sym) {
    void* p = nullptr;
    cudaGetSymbolAddress(&p, sym);
    return (float*)p;
}

extern "C" void kernel_launch(void* const* d_in, const int* in_sizes, int n_in,
                              void* d_out, int out_size)
{
    const float* x   = (const float*)d_in[0];
    const float* Wd  = (const float*)d_in[1];
    const float* Wuk = (const float*)d_in[2];
    const float* Wuv = (const float*)d_in[3];
    const float* Wq  = (const float*)d_in[4];
    const float* Wo  = (const float*)d_in[5];
    float* out = (float*)d_out;

    float* latents = symaddr(g_latents);
    float* quk     = symaddr(g_quk);
    float* ouv     = symaddr(g_ouv);
    float* q       = symaddr(g_q);
    float* scores  = symaddr(g_scores);
    float* ctx     = symaddr(g_ctx);

    dim3 blk(256);
    const size_t MC = (size_t)D_MODEL * CLAT;   // 2048*512
    const size_t SC = (size_t)SEQ * CLAT;       // 2048*512
    const size_t SS = (size_t)SEQ * SEQ;        // 2048*2048

    // 1. latents[b*s, c] = x[b*s, m] @ Wd[c, m]^T          (NT, K=2048)
    gemm_k<false, true><<<dim3(CLAT / BN, BS / BM, 1), blk>>>(
        x, Wd, latents, BS, CLAT, D_MODEL, D_MODEL, D_MODEL, CLAT,
        0, 0, 0, 1, 1, 0, 0, 0);

    // 2. q_uk[h][m][c] = sum_d Wq[h*128+d][m] * Wuk[h*128+d][c]   (TN, K=128)
    gemm_k<true, false><<<dim3(CLAT / BN, D_MODEL / BM, NHEADS), blk>>>(
        Wq, Wuk, quk, D_MODEL, CLAT, D_HEAD, D_MODEL, CLAT, CLAT,
        (size_t)D_HEAD * D_MODEL, (size_t)D_HEAD * CLAT, MC, NHEADS, 1, 0, 0, 0);

    // 3. out_uv[h][m][c] = sum_d Wo[m][h*128+d] * Wuv[h*128+d][c]  (NN, K=128)
    gemm_k<false, false><<<dim3(CLAT / BN, D_MODEL / BM, NHEADS), blk>>>(
        Wo, Wuv, ouv, D_MODEL, CLAT, D_HEAD, D_MODEL, CLAT, CLAT,
        (size_t)D_HEAD, (size_t)D_HEAD * CLAT, MC, NHEADS, 1, 0, 0, 0);

    // 4. q[h][b*s][c] = x[b*s, m] @ q_uk[h][m][c]          (NN, K=2048)
    gemm_k<false, false><<<dim3(CLAT / BN, BS / BM, NHEADS), blk>>>(
        x, quk, q, BS, CLAT, D_MODEL, D_MODEL, CLAT, CLAT,
        0, MC, (size_t)BS * CLAT, NHEADS, 1, 0, 0, 0);

    // 5. scores[(h,b)][s][t] = q_hb[s,c] @ latents_b[t,c]^T   (NT, K=512, causal skip)
    //    z = h*2+b:  q offset = z*SEQ*CLAT ; latents offset = (z%2)*SEQ*CLAT
    gemm_k<false, true><<<dim3(SEQ / BN, SEQ / BM, NHEADS * BATCH), blk>>>(
        q, latents, scores, SEQ, SEQ, CLAT, CLAT, CLAT, SEQ,
        SC, SC, SS, BATCH, 1, 0, 0, 1);

    // 6. causal softmax (scale = 1/sqrt(128)), zero-fill masked tail
    softmax_causal_k<<<NHEADS * BATCH * SEQ, blk>>>(scores, 0.08838834764831845f);

    // 7. ctx[(h,b)][s][c] = attn[s,t] @ latents_b[t,c]      (NN, K truncated causally)
    gemm_k<false, false><<<dim3(CLAT / BN, SEQ / BM, NHEADS * BATCH), blk>>>(
        scores, latents, ctx, SEQ, CLAT, SEQ, SEQ, CLAT, CLAT,
        SS, SC, SC, BATCH, 1, 0, 0, 2);

    // 8. out[b*s, m] = sum_h ctx[h][b*s, c] @ out_uv[h][m, c]^T   (NT, inner L=16)
    gemm_k<false, true><<<dim3(D_MODEL / BN, BS / BM, 1), blk>>>(
        ctx, ouv, out, BS, D_MODEL, CLAT, CLAT, CLAT, D_MODEL,
        0, 0, 0, 1, NHEADS, (size_t)BS * CLAT, MC, 0);
}

// round 6
// speedup vs baseline: 3.7378x; 3.7378x over previous
#include <cuda_runtime.h>
#include <cuda_bf16.h>
#include <math.h>
#include <stdint.h>

// Problem constants
#define D_MODEL 2048
#define D_HEAD  128
#define NHEADS  16
#define CLAT    512
#define BATCH   2
#define SEQ     2048
#define BS      (BATCH*SEQ)   // 4096

// Scratch (allocation-free rule: __device__ globals)
__device__ float g_latents[(size_t)BS * CLAT];                  //   8 MB [bs][c]
__device__ float g_latT[(size_t)BATCH * CLAT * SEQ];            //   8 MB [b][c][t]
__device__ float g_wukT[(size_t)CLAT * NHEADS * D_HEAD];        //   4 MB [c][hd]
__device__ float g_qh[(size_t)BS * NHEADS * D_HEAD];            //  32 MB [bs][hd]
__device__ float g_q[(size_t)NHEADS * BS * CLAT];               // 128 MB [h][bs][c]
__device__ float g_scores[(size_t)NHEADS * BATCH * SEQ * SEQ];  // 512 MB [(h,b)][s][t]
__device__ float g_ctx[(size_t)NHEADS * BS * CLAT];             // 128 MB [(h,b)][s][c]
__device__ float g_v[(size_t)BS * NHEADS * D_HEAD];             //  32 MB [bs][hd]

// ---------------- mma.sync / ldmatrix primitives (baseline PTX, sm_80+) ----
__device__ __forceinline__ uint32_t smem_u32(const void* p) {
    uint32_t a;
    asm("{ .reg .u64 t; cvta.to.shared.u64 t, %1; cvt.u32.u64 %0, t; }" : "=r"(a) : "l"(p));
    return a;
}
__device__ __forceinline__ void ldsm_x4(uint32_t addr, uint32_t r[4]) {
    asm volatile("ldmatrix.sync.aligned.m8n8.x4.shared.b16 {%0,%1,%2,%3}, [%4];"
        : "=r"(r[0]), "=r"(r[1]), "=r"(r[2]), "=r"(r[3]) : "r"(addr));
}
__device__ __forceinline__ void mma16816(float c[4], const uint32_t a[4], const uint32_t b[2]) {
    asm volatile(
        "mma.sync.aligned.m16n8k16.row.col.f32.bf16.bf16.f32 "
        "{%0,%1,%2,%3}, {%4,%5,%6,%7}, {%8,%9}, {%0,%1,%2,%3};"
        : "+f"(c[0]), "+f"(c[1]), "+f"(c[2]), "+f"(c[3])
        : "r"(a[0]), "r"(a[1]), "r"(a[2]), "r"(a[3]), "r"(b[0]), "r"(b[1]));
}

// SMEM tile geometry: 128 rows x 32 k bf16, row stride 40 b16 = 80 B
#define ROWB 80
#define TILEB (128 * ROWB)            // 10240 B per (hi|lo) x (A|B) quarter
#define STAGEB (4 * TILEB)            // 40960 B per stage
#define SMEM_BYTES (2 * STAGEB + 128) // double buffered

// fp32 -> (hi,lo) bf16 split, 4 elements, 8B stores
__device__ __forceinline__ void cvt_store(char* hi, char* lo, uint32_t off, float4 v) {
    __nv_bfloat162 h0 = __float22bfloat162_rn(make_float2(v.x, v.y));
    __nv_bfloat162 h1 = __float22bfloat162_rn(make_float2(v.z, v.w));
    __nv_bfloat162 l0 = __float22bfloat162_rn(make_float2(v.x - __low2float(h0), v.y - __high2float(h0)));
    __nv_bfloat162 l1 = __float22bfloat162_rn(make_float2(v.z - __low2float(h1), v.w - __high2float(h1)));
    uint2 hv, lv;
    hv.x = *(uint32_t*)&h0; hv.y = *(uint32_t*)&h1;
    lv.x = *(uint32_t*)&l0; lv.y = *(uint32_t*)&l1;
    *(uint2*)(hi + off) = hv;
    *(uint2*)(lo + off) = lv;
}

// ---------------- split-bf16 tensor-core GEMM ----------------
// C[z][M,N](+offsets) = A[z][M,K] @ B[z][N,K]^T   (A row-major [m][k], B [n][k])
// A += z*sAz ; B += ((z/zBdiv)%zBmod)*sBz ; C += (z/zCdiv)*sCz + (z%zCdiv)*sCz2
// causalMode: 0 none; 1 skip bn>bm; 2 truncate K at (bm+1)*128
__global__ __launch_bounds__(256) void gemm_mma(
    const float* __restrict__ A, const float* __restrict__ B, float* __restrict__ C,
    int K, int lda, int ldb, int ldc,
    size_t sAz, size_t sBz, int zBdiv, int zBmod,
    size_t sCz, size_t sCz2, int zCdiv, int causalMode)
{
    int bn = blockIdx.x, bm = blockIdx.y, z = blockIdx.z;
    if (causalMode == 1 && bn > bm) return;
    int Kend = K;
    if (causalMode == 2) { int lim = (bm + 1) * 128; if (lim < Kend) Kend = lim; }

    A += (size_t)z * sAz;
    B += (size_t)((z / zBdiv) % zBmod) * sBz;
    C += (size_t)(z / zCdiv) * sCz + (size_t)(z % zCdiv) * sCz2;

    extern __shared__ char smraw[];
    char* sm = (char*)(((uintptr_t)smraw + 127) & ~(uintptr_t)127);
    uint32_t sbase = smem_u32(sm);

    int tid = threadIdx.x;
    int wid = tid >> 5, lane = tid & 31;
    int m0 = bm * 128, n0 = bn * 128;

    // staging: thread t covers row t>>1, k-half (t&1)*16
    int srow = tid >> 1;
    int skb  = (tid & 1) * 16;
    const float* pA = A + (size_t)(m0 + srow) * lda + skb;
    const float* pB = B + (size_t)(n0 + srow) * ldb + skb;
    uint32_t soff = (uint32_t)srow * ROWB + (uint32_t)skb * 2;

    // warp tiling: 2x4 warp grid, warp tile 64x32
    int wm = wid & 1, wn = wid >> 1;
    int m0w = wm * 64, n0w = wn * 32;

    uint32_t aRow = (uint32_t)(m0w + (lane & 15));
    uint32_t aK8  = (uint32_t)((lane >> 4) * 8);
    uint32_t bRow = (uint32_t)(n0w + (lane & 7) + ((lane >> 4) & 1) * 8);
    uint32_t bK8  = (uint32_t)(((lane >> 3) & 1) * 8);

    float acc[4][4][4];
#pragma unroll
    for (int i = 0; i < 4; i++)
#pragma unroll
        for (int j = 0; j < 4; j++)
#pragma unroll
            for (int r = 0; r < 4; r++) acc[i][j][r] = 0.f;

    int ncha = Kend / 32;
    float4 ra[4], rb[4];

    // prologue: chunk 0
#pragma unroll
    for (int i = 0; i < 4; i++) { ra[i] = *(const float4*)(pA + i * 4); rb[i] = *(const float4*)(pB + i * 4); }
    {
        char* base = sm;
#pragma unroll
        for (int i = 0; i < 4; i++) {
            cvt_store(base, base + TILEB, soff + i * 8, ra[i]);
            cvt_store(base + 2 * TILEB, base + 3 * TILEB, soff + i * 8, rb[i]);
        }
    }
    __syncthreads();

    for (int c = 0; c < ncha; c++) {
        if (c + 1 < ncha) {
            const float* nA = pA + (size_t)(c + 1) * 32;
            const float* nB = pB + (size_t)(c + 1) * 32;
#pragma unroll
            for (int i = 0; i < 4; i++) { ra[i] = *(const float4*)(nA + i * 4); rb[i] = *(const float4*)(nB + i * 4); }
        }

        uint32_t sb = sbase + (uint32_t)(c & 1) * STAGEB;
        uint32_t sbAh = sb, sbAl = sb + TILEB, sbBh = sb + 2 * TILEB, sbBl = sb + 3 * TILEB;

#pragma unroll
        for (int ks = 0; ks < 2; ks++) {
            uint32_t k0 = (uint32_t)(ks * 16);
            uint32_t Ah[4][4], Al[4][4], Bh[2][4], Bl[2][4];
#pragma unroll
            for (int im = 0; im < 4; im++) {
                uint32_t ao = (aRow + im * 16) * ROWB + (k0 + aK8) * 2;
                ldsm_x4(sbAh + ao, Ah[im]);
                ldsm_x4(sbAl + ao, Al[im]);
            }
#pragma unroll
            for (int p = 0; p < 2; p++) {
                uint32_t bo = (bRow + p * 16) * ROWB + (k0 + bK8) * 2;
                ldsm_x4(sbBh + bo, Bh[p]);
                ldsm_x4(sbBl + bo, Bl[p]);
            }
#pragma unroll
            for (int im = 0; im < 4; im++)
#pragma unroll
                for (int in_ = 0; in_ < 4; in_++) {
                    int p = in_ >> 1, q = (in_ & 1) * 2;
                    mma16816(acc[im][in_], Ah[im], &Bh[p][q]);
                    mma16816(acc[im][in_], Ah[im], &Bl[p][q]);
                    mma16816(acc[im][in_], Al[im], &Bh[p][q]);
                }
        }
        __syncthreads();
        if (c + 1 < ncha) {
            char* base = sm + ((c + 1) & 1) * STAGEB;
#pragma unroll
            for (int i = 0; i < 4; i++) {
                cvt_store(base, base + TILEB, soff + i * 8, ra[i]);
                cvt_store(base + 2 * TILEB, base + 3 * TILEB, soff + i * 8, rb[i]);
            }
            __syncthreads();
        }
    }

    // epilogue: acc -> C
#pragma unroll
    for (int im = 0; im < 4; im++) {
        int r0 = m0 + m0w + im * 16 + (lane >> 2);
#pragma unroll
        for (int in_ = 0; in_ < 4; in_++) {
            int c0 = n0 + n0w + in_ * 8 + (lane & 3) * 2;
            *(float2*)&C[(size_t)r0 * ldc + c0]       = make_float2(acc[im][in_][0], acc[im][in_][1]);
            *(float2*)&C[(size_t)(r0 + 8) * ldc + c0] = make_float2(acc[im][in_][2], acc[im][in_][3]);
        }
    }
}

// ---------------- 32x32 tiled transpose: out[z][c][r] = in[z][r][c] -------
// REQUIRES block = dim3(32, 8)
__global__ void transpose_k(
    const float* __restrict__ in, float* __restrict__ out, int R, int C,
    size_t inz, size_t outz)
{
    __shared__ float t[32][33];
    const float* pi = in + (size_t)blockIdx.z * inz;
    float* po = out + (size_t)blockIdx.z * outz;
    int c = blockIdx.x * 32 + threadIdx.x;
    int r0 = blockIdx.y * 32 + threadIdx.y;
#pragma unroll
    for (int i = 0; i < 32; i += 8)
        t[threadIdx.y + i][threadIdx.x] = pi[(size_t)(r0 + i) * C + c];
    __syncthreads();
    int rc = blockIdx.y * 32 + threadIdx.x;
    int cr0 = blockIdx.x * 32 + threadIdx.y;
#pragma unroll
    for (int i = 0; i < 32; i += 8)
        po[(size_t)(cr0 + i) * R + rc] = t[threadIdx.x][threadIdx.y + i];
}

// ---------------- causal softmax (passed in R2) ----------------
__global__ __launch_bounds__(256) void softmax_causal_k(float* __restrict__ scores, float scale)
{
    int r = blockIdx.x;
    int z = r >> 11;
    int s = r & (SEQ - 1);
    float* p = scores + ((size_t)z * SEQ + (size_t)s) * SEQ;
    int n = s + 1;
    int tid = threadIdx.x;
    __shared__ float red[256];

    float m = -3.0e38f;
    for (int j = tid; j < n; j += 256) m = fmaxf(m, p[j]);
    red[tid] = m; __syncthreads();
    for (int o = 128; o > 0; o >>= 1) { if (tid < o) red[tid] = fmaxf(red[tid], red[tid + o]); __syncthreads(); }
    m = red[0]; __syncthreads();

    float sum = 0.f;
    for (int j = tid; j < n; j += 256) {
        float e = expf((p[j] - m) * scale);
        p[j] = e;
        sum += e;
    }
    red[tid] = sum; __syncthreads();
    for (int o = 128; o > 0; o >>= 1) { if (tid < o) red[tid] += red[tid + o]; __syncthreads(); }
    float inv = 1.f / red[0];
    __syncthreads();

    for (int j = tid; j < n; j += 256) p[j] *= inv;
    for (int j = n + tid; j < SEQ; j += 256) p[j] = 0.f;
}

static float* symaddr(const void* sym) {
    void* p = nullptr;
    cudaGetSymbolAddress(&p, sym);
    return (float*)p;
}

extern "C" void kernel_launch(void* const* d_in, const int* in_sizes, int n_in,
                              void* d_out, int out_size)
{
    const float* x   = (const float*)d_in[0];
    const float* Wd  = (const float*)d_in[1];
    const float* Wuk = (const float*)d_in[2];
    const float* Wuv = (const float*)d_in[3];
    const float* Wq  = (const float*)d_in[4];
    const float* Wo  = (const float*)d_in[5];
    float* out = (float*)d_out;

    float* latents = symaddr(g_latents);
    float* latT    = symaddr(g_latT);
    float* wukT    = symaddr(g_wukT);
    float* qh      = symaddr(g_qh);
    float* q       = symaddr(g_q);
    float* scores  = symaddr(g_scores);
    float* ctx     = symaddr(g_ctx);
    float* v       = symaddr(g_v);

    cudaFuncSetAttribute(gemm_mma, cudaFuncAttributeMaxDynamicSharedMemorySize, SMEM_BYTES);

    dim3 blk(256);
    dim3 tblk(32, 8);
    const size_t SC = (size_t)SEQ * CLAT;     // 1048576
    const size_t SS = (size_t)SEQ * SEQ;      // 4194304

    // 0. wukT[c][hd] = Wuk[hd][c]^T
    transpose_k<<<dim3(CLAT / 32, (NHEADS * D_HEAD) / 32, 1), tblk>>>(
        Wuk, wukT, NHEADS * D_HEAD, CLAT, 0, 0);

    // 1. latents[bs][c] = x @ Wd^T   (M=4096,N=512,K=2048)
    gemm_mma<<<dim3(CLAT / 128, BS / 128, 1), blk, SMEM_BYTES>>>(
        x, Wd, latents, D_MODEL, D_MODEL, D_MODEL, CLAT,
        0, 0, 1, 1, 0, 0, 1, 0);

    // 1b. latT[b][c][t] = latents[b][t][c]^T
    transpose_k<<<dim3(CLAT / 32, SEQ / 32, BATCH), tblk>>>(
        latents, latT, SEQ, CLAT, SC, SC);

    // 2. qh[bs][hd] = x @ Wq^T       (M=4096,N=2048,K=2048)
    gemm_mma<<<dim3((NHEADS * D_HEAD) / 128, BS / 128, 1), blk, SMEM_BYTES>>>(
        x, Wq, qh, D_MODEL, D_MODEL, D_MODEL, NHEADS * D_HEAD,
        0, 0, 1, 1, 0, 0, 1, 0);

    // 3. q[h][bs][c] = qh[:,h*128:+128] @ wukT[:,h*128:+128]^T  (M=4096,N=512,K=128)
    gemm_mma<<<dim3(CLAT / 128, BS / 128, NHEADS), blk, SMEM_BYTES>>>(
        qh, wukT, q, D_HEAD, NHEADS * D_HEAD, NHEADS * D_HEAD, CLAT,
        (size_t)D_HEAD, (size_t)D_HEAD, 1, NHEADS,
        (size_t)BS * CLAT, 0, 1, 0);

    // 4. scores[(h,b)][s][t] = q_hb @ latents_b^T  (M=N=2048,K=512, causal skip)
    gemm_mma<<<dim3(SEQ / 128, SEQ / 128, NHEADS * BATCH), blk, SMEM_BYTES>>>(
        q, latents, scores, CLAT, CLAT, CLAT, SEQ,
        SC, SC, 1, BATCH, SS, 0, 1, 1);

    // 5. causal softmax (scale = 1/sqrt(128))
    softmax_causal_k<<<NHEADS * BATCH * SEQ, blk>>>(scores, 0.08838834764831845f);

    // 6. ctx[(h,b)][s][c] = attn @ latT_b^T  (M=2048,N=512,K=SEQ trunc)
    gemm_mma<<<dim3(CLAT / 128, SEQ / 128, NHEADS * BATCH), blk, SMEM_BYTES>>>(
        scores, latT, ctx, SEQ, SEQ, SEQ, CLAT,
        SS, SC, 1, BATCH, SC, 0, 1, 2);

    // 7. v[(b,s)][h*128+d] = ctx_hb @ Wuv_h^T  (M=2048,N=128,K=512)
    gemm_mma<<<dim3(1, SEQ / 128, NHEADS * BATCH), blk, SMEM_BYTES>>>(
        ctx, Wuv, v, CLAT, CLAT, CLAT, NHEADS * D_HEAD,
        SC, (size_t)D_HEAD * CLAT, 2, NHEADS,
        (size_t)D_HEAD, (size_t)SEQ * NHEADS * D_HEAD, 2, 0);

    // 8. out[bs][m] = v @ Wo^T       (M=4096,N=2048,K=2048)
    gemm_mma<<<dim3(D_MODEL / 128, BS / 128, 1), blk, SMEM_BYTES>>>(
        v, Wo, out, NHEADS * D_HEAD, NHEADS * D_HEAD, NHEADS * D_HEAD, D_MODEL,
        0, 0, 1, 1, 0, 0, 1, 0);
}

// round 9
// speedup vs baseline: 6.0661x; 1.6229x over previous
#include <cuda_runtime.h>
#include <cuda_bf16.h>
#include <math.h>
#include <stdint.h>

// Problem constants
#define D_MODEL 2048
#define D_HEAD  128
#define NHEADS  16
#define CLAT    512
#define BATCH   2
#define SEQ     2048
#define BS      (BATCH*SEQ)   // 4096

// Scratch (allocation-free rule: __device__ globals)
__device__ float g_latents[(size_t)BS * CLAT];                  //   8 MB [bs][c]
__device__ float g_qh[(size_t)BS * NHEADS * D_HEAD];            //  32 MB [bs][hd]
__device__ float g_k[(size_t)NHEADS * BS * D_HEAD];             //  32 MB [(2h+b)][t][128]
__device__ float g_v[(size_t)NHEADS * BS * D_HEAD];             //  32 MB [(2h+b)][t][128]
__device__ float g_vT[(size_t)NHEADS * BS * D_HEAD];            //  32 MB [(2h+b)][128][t]
__device__ float g_scores[(size_t)NHEADS * BATCH * SEQ * SEQ];  // 512 MB [(2h+b)][s][t]
__device__ float g_ctxv[(size_t)BS * NHEADS * D_HEAD];          //  32 MB [bs][hd]

// ---------------- mma.sync / ldmatrix primitives (baseline PTX, sm_80+) ----
__device__ __forceinline__ uint32_t smem_u32(const void* p) {
    uint32_t a;
    asm("{ .reg .u64 t; cvta.to.shared.u64 t, %1; cvt.u32.u64 %0, t; }" : "=r"(a) : "l"(p));
    return a;
}
__device__ __forceinline__ void ldsm_x4(uint32_t addr, uint32_t r[4]) {
    asm volatile("ldmatrix.sync.aligned.m8n8.x4.shared.b16 {%0,%1,%2,%3}, [%4];"
        : "=r"(r[0]), "=r"(r[1]), "=r"(r[2]), "=r"(r[3]) : "r"(addr));
}
__device__ __forceinline__ void mma16816(float c[4], const uint32_t a[4], const uint32_t b[2]) {
    asm volatile(
        "mma.sync.aligned.m16n8k16.row.col.f32.bf16.bf16.f32 "
        "{%0,%1,%2,%3}, {%4,%5,%6,%7}, {%8,%9}, {%0,%1,%2,%3};"
        : "+f"(c[0]), "+f"(c[1]), "+f"(c[2]), "+f"(c[3])
        : "r"(a[0]), "r"(a[1]), "r"(a[2]), "r"(a[3]), "r"(b[0]), "r"(b[1]));
}

// SMEM tile geometry: 128 rows x 32 k bf16, row stride 40 b16 = 80 B
#define ROWB 80
#define TILEB (128 * ROWB)            // 10240 B per (hi|lo) x (A|B) quarter
#define STAGEB (4 * TILEB)            // 40960 B per stage
#define SMEM_BYTES (2 * STAGEB + 128) // double buffered

// fp32 -> (hi,lo) bf16 split, 4 elements, 8B stores
__device__ __forceinline__ void cvt_store(char* hi, char* lo, uint32_t off, float4 v) {
    __nv_bfloat162 h0 = __float22bfloat162_rn(make_float2(v.x, v.y));
    __nv_bfloat162 h1 = __float22bfloat162_rn(make_float2(v.z, v.w));
    __nv_bfloat162 l0 = __float22bfloat162_rn(make_float2(v.x - __low2float(h0), v.y - __high2float(h0)));
    __nv_bfloat162 l1 = __float22bfloat162_rn(make_float2(v.z - __low2float(h1), v.w - __high2float(h1)));
    uint2 hv, lv;
    hv.x = *(uint32_t*)&h0; hv.y = *(uint32_t*)&h1;
    lv.x = *(uint32_t*)&l0; lv.y = *(uint32_t*)&l1;
    *(uint2*)(hi + off) = hv;
    *(uint2*)(lo + off) = lv;
}

// ---------------- split-bf16 tensor-core GEMM ----------------
// C[z][M,N] = A[z][M,K] @ B[z][N,K]^T   (A row-major [m][k], B [n][k])
// A += (z/zAdiv)*sAz + (z%zAdiv)*sAz2
// B += (z%zBmod)*sBz
// C += (z/zCdiv)*sCz + (z%zCdiv)*sCz2
// causalMode: 0 none; 1 skip bn>bm; 2 truncate K at (bm+1)*128
__global__ __launch_bounds__(256) void gemm_mma(
    const float* __restrict__ A, const float* __restrict__ B, float* __restrict__ C,
    int K, int lda, int ldb, int ldc,
    size_t sAz, size_t sAz2, int zAdiv,
    size_t sBz, int zBmod,
    size_t sCz, size_t sCz2, int zCdiv, int causalMode)
{
    int bn = blockIdx.x, bm = blockIdx.y, z = blockIdx.z;
    if (causalMode == 1 && bn > bm) return;
    int Kend = K;
    if (causalMode == 2) { int lim = (bm + 1) * 128; if (lim < Kend) Kend = lim; }

    A += (size_t)(z / zAdiv) * sAz + (size_t)(z % zAdiv) * sAz2;
    B += (size_t)(z % zBmod) * sBz;
    C += (size_t)(z / zCdiv) * sCz + (size_t)(z % zCdiv) * sCz2;

    extern __shared__ char smraw[];
    char* sm = (char*)(((uintptr_t)smraw + 127) & ~(uintptr_t)127);
    uint32_t sbase = smem_u32(sm);

    int tid = threadIdx.x;
    int wid = tid >> 5, lane = tid & 31;
    int m0 = bm * 128, n0 = bn * 128;

    // staging: thread t covers row t>>1, k-half (t&1)*16
    int srow = tid >> 1;
    int skb  = (tid & 1) * 16;
    const float* pA = A + (size_t)(m0 + srow) * lda + skb;
    const float* pB = B + (size_t)(n0 + srow) * ldb + skb;
    uint32_t soff = (uint32_t)srow * ROWB + (uint32_t)skb * 2;

    // warp tiling: 2x4 warp grid, warp tile 64x32
    int wm = wid & 1, wn = wid >> 1;
    int m0w = wm * 64, n0w = wn * 32;

    uint32_t aRow = (uint32_t)(m0w + (lane & 15));
    uint32_t aK8  = (uint32_t)((lane >> 4) * 8);
    uint32_t bRow = (uint32_t)(n0w + (lane & 7) + ((lane >> 4) & 1) * 8);
    uint32_t bK8  = (uint32_t)(((lane >> 3) & 1) * 8);

    float acc[4][4][4];
#pragma unroll
    for (int i = 0; i < 4; i++)
#pragma unroll
        for (int j = 0; j < 4; j++)
#pragma unroll
            for (int r = 0; r < 4; r++) acc[i][j][r] = 0.f;

    int ncha = Kend / 32;
    float4 ra[4], rb[4];

    // prologue: stage chunk 0
#pragma unroll
    for (int i = 0; i < 4; i++) { ra[i] = *(const float4*)(pA + i * 4); rb[i] = *(const float4*)(pB + i * 4); }
    {
        char* base = sm;
#pragma unroll
        for (int i = 0; i < 4; i++) {
            cvt_store(base, base + TILEB, soff + i * 8, ra[i]);
            cvt_store(base + 2 * TILEB, base + 3 * TILEB, soff + i * 8, rb[i]);
        }
    }
    __syncthreads();

    for (int c = 0; c < ncha; c++) {
        if (c + 1 < ncha) {
            const float* nA = pA + (size_t)(c + 1) * 32;
            const float* nB = pB + (size_t)(c + 1) * 32;
#pragma unroll
            for (int i = 0; i < 4; i++) { ra[i] = *(const float4*)(nA + i * 4); rb[i] = *(const float4*)(nB + i * 4); }
        }

        uint32_t sb = sbase + (uint32_t)(c & 1) * STAGEB;
        uint32_t sbAh = sb, sbAl = sb + TILEB, sbBh = sb + 2 * TILEB, sbBl = sb + 3 * TILEB;

#pragma unroll
        for (int ks = 0; ks < 2; ks++) {
            uint32_t k0 = (uint32_t)(ks * 16);
            uint32_t Ah[4][4], Al[4][4], Bh[2][4], Bl[2][4];
#pragma unroll
            for (int im = 0; im < 4; im++) {
                uint32_t ao = (aRow + im * 16) * ROWB + (k0 + aK8) * 2;
                ldsm_x4(sbAh + ao, Ah[im]);
                ldsm_x4(sbAl + ao, Al[im]);
            }
#pragma unroll
            for (int p = 0; p < 2; p++) {
                uint32_t bo = (bRow + p * 16) * ROWB + (k0 + bK8) * 2;
                ldsm_x4(sbBh + bo, Bh[p]);
                ldsm_x4(sbBl + bo, Bl[p]);
            }
#pragma unroll
            for (int im = 0; im < 4; im++)
#pragma unroll
                for (int in_ = 0; in_ < 4; in_++) {
                    int p = in_ >> 1, q = (in_ & 1) * 2;
                    mma16816(acc[im][in_], Ah[im], &Bh[p][q]);
                    mma16816(acc[im][in_], Ah[im], &Bl[p][q]);
                    mma16816(acc[im][in_], Al[im], &Bh[p][q]);
                }
        }

        // single sync per chunk: store next chunk into the other buffer, then sync
        if (c + 1 < ncha) {
            char* base = sm + ((c + 1) & 1) * STAGEB;
#pragma unroll
            for (int i = 0; i < 4; i++) {
                cvt_store(base, base + TILEB, soff + i * 8, ra[i]);
                cvt_store(base + 2 * TILEB, base + 3 * TILEB, soff + i * 8, rb[i]);
            }
            __syncthreads();
        }
    }

    // epilogue: acc -> C
#pragma unroll
    for (int im = 0; im < 4; im++) {
        int r0 = m0 + m0w + im * 16 + (lane >> 2);
#pragma unroll
        for (int in_ = 0; in_ < 4; in_++) {
            int c0 = n0 + n0w + in_ * 8 + (lane & 3) * 2;
            *(float2*)&C[(size_t)r0 * ldc + c0]       = make_float2(acc[im][in_][0], acc[im][in_][1]);
            *(float2*)&C[(size_t)(r0 + 8) * ldc + c0] = make_float2(acc[im][in_][2], acc[im][in_][3]);
        }
    }
}

// ---------------- 32x32 tiled transpose: out[z][c][r] = in[z][r][c] -------
// REQUIRES block = dim3(32, 8)
__global__ void transpose_k(
    const float* __restrict__ in, float* __restrict__ out, int R, int C,
    size_t inz, size_t outz)
{
    __shared__ float t[32][33];
    const float* pi = in + (size_t)blockIdx.z * inz;
    float* po = out + (size_t)blockIdx.z * outz;
    int c = blockIdx.x * 32 + threadIdx.x;
    int r0 = blockIdx.y * 32 + threadIdx.y;
#pragma unroll
    for (int i = 0; i < 32; i += 8)
        t[threadIdx.y + i][threadIdx.x] = pi[(size_t)(r0 + i) * C + c];
    __syncthreads();
    int rc = blockIdx.y * 32 + threadIdx.x;
    int cr0 = blockIdx.x * 32 + threadIdx.y;
#pragma unroll
    for (int i = 0; i < 32; i += 8)
        po[(size_t)(cr0 + i) * R + rc] = t[threadIdx.x][threadIdx.y + i];
}

// ---------------- causal softmax, SMEM-resident row ----------------
// one global read + one global write; zero-fill only to next 128-boundary
__global__ __launch_bounds__(256) void softmax_causal_k(float* __restrict__ scores, float scale)
{
    __shared__ float srow[SEQ];
    __shared__ float red[256];
    int r = blockIdx.x;
    int z = r >> 11;                    // SEQ == 2048
    int s = r & (SEQ - 1);
    float* p = scores + ((size_t)z * SEQ + (size_t)s) * SEQ;
    int n = s + 1;
    int tid = threadIdx.x;

    float m = -3.0e38f;
    for (int j = tid; j < n; j += 256) { float vv = p[j]; srow[j] = vv; m = fmaxf(m, vv); }
    red[tid] = m; __syncthreads();
    for (int o = 128; o > 0; o >>= 1) { if (tid < o) red[tid] = fmaxf(red[tid], red[tid + o]); __syncthreads(); }
    m = red[0]; __syncthreads();

    float sum = 0.f;
    for (int j = tid; j < n; j += 256) {
        float e = expf((srow[j] - m) * scale);
        srow[j] = e;
        sum += e;
    }
    red[tid] = sum; __syncthreads();
    for (int o = 128; o > 0; o >>= 1) { if (tid < o) red[tid] += red[tid + o]; __syncthreads(); }
    float inv = 1.f / red[0];

    for (int j = tid; j < n; j += 256) p[j] = srow[j] * inv;
    int zend = ((s >> 7) + 1) << 7;     // ctx truncates K at this boundary
    for (int j = n + tid; j < zend; j += 256) p[j] = 0.f;
}

static float* symaddr(const void* sym) {
    void* p = nullptr;
    cudaGetSymbolAddress(&p, sym);
    return (float*)p;
}

extern "C" void kernel_launch(void* const* d_in, const int* in_sizes, int n_in,
                              void* d_out, int out_size)
{
    const float* x   = (const float*)d_in[0];
    const float* Wd  = (const float*)d_in[1];
    const float* Wuk = (const float*)d_in[2];
    const float* Wuv = (const float*)d_in[3];
    const float* Wq  = (const float*)d_in[4];
    const float* Wo  = (const float*)d_in[5];
    float* out = (float*)d_out;

    float* latents = symaddr(g_latents);
    float* qh      = symaddr(g_qh);
    float* kbuf    = symaddr(g_k);
    float* vbuf    = symaddr(g_v);
    float* vT      = symaddr(g_vT);
    float* scores  = symaddr(g_scores);
    float* ctxv    = symaddr(g_ctxv);

    cudaFuncSetAttribute(gemm_mma, cudaFuncAttributeMaxDynamicSharedMemorySize, SMEM_BYTES);

    dim3 blk(256);
    dim3 tblk(32, 8);
    const int HD = NHEADS * D_HEAD;           // 2048
    const size_t SS  = (size_t)SEQ * SEQ;     // 4194304
    const size_t SD  = (size_t)SEQ * D_HEAD;  // 262144  (per (h,b) k/v slab)
    const size_t BSD = (size_t)BS * D_HEAD;   // 524288  (per h k/v slab)

    // 1. latents[bs][c] = x @ Wd^T   (M=4096,N=512,K=2048)
    gemm_mma<<<dim3(CLAT / 128, BS / 128, 1), blk, SMEM_BYTES>>>(
        x, Wd, latents, D_MODEL, D_MODEL, D_MODEL, CLAT,
        0, 0, 1, 0, 1, 0, 0, 1, 0);

    // 2. qh[bs][hd] = x @ Wq^T       (M=4096,N=2048,K=2048)
    gemm_mma<<<dim3(HD / 128, BS / 128, 1), blk, SMEM_BYTES>>>(
        x, Wq, qh, D_MODEL, D_MODEL, D_MODEL, HD,
        0, 0, 1, 0, 1, 0, 0, 1, 0);

    // 3. k[h][bs][128] = latents @ Wuk_h^T   (M=4096,N=128,K=512, z=h)
    gemm_mma<<<dim3(1, BS / 128, NHEADS), blk, SMEM_BYTES>>>(
        latents, Wuk, kbuf, CLAT, CLAT, CLAT, D_HEAD,
        0, 0, 1, (size_t)D_HEAD * CLAT, NHEADS, BSD, 0, 1, 0);

    // 4. v[h][bs][128] = latents @ Wuv_h^T   (M=4096,N=128,K=512, z=h)
    gemm_mma<<<dim3(1, BS / 128, NHEADS), blk, SMEM_BYTES>>>(
        latents, Wuv, vbuf, CLAT, CLAT, CLAT, D_HEAD,
        0, 0, 1, (size_t)D_HEAD * CLAT, NHEADS, BSD, 0, 1, 0);

    // 4b. vT[(2h+b)][128][t] = v[(2h+b)][t][128]^T  (32 slabs)
    transpose_k<<<dim3(D_HEAD / 32, SEQ / 32, NHEADS * BATCH), tblk>>>(
        vbuf, vT, SEQ, D_HEAD, SD, SD);

    // 5. scores[(2h+b)][s][t] = qh_slice @ k_hb^T  (M=N=2048,K=128, causal skip)
    //    A offset: h*128 cols + b*SEQ*HD rows ; B offset: z*SEQ*128
    gemm_mma<<<dim3(SEQ / 128, SEQ / 128, NHEADS * BATCH), blk, SMEM_BYTES>>>(
        qh, kbuf, scores, D_HEAD, HD, D_HEAD, SEQ,
        (size_t)D_HEAD, (size_t)SEQ * HD, 2,
        SD, NHEADS * BATCH, SS, 0, 1, 1);

    // 6. causal softmax (scale = 1/sqrt(128))
    softmax_causal_k<<<NHEADS * BATCH * SEQ, blk>>>(scores, 0.08838834764831845f);

    // 7. ctxv[(b,s)][h*128+d] = attn @ vT_hb^T  (M=2048,N=128,K=SEQ trunc)
    gemm_mma<<<dim3(1, SEQ / 128, NHEADS * BATCH), blk, SMEM_BYTES>>>(
        scores, vT, ctxv, SEQ, SEQ, SEQ, HD,
        SS, 0, 1, SD, NHEADS * BATCH,
        (size_t)D_HEAD, (size_t)SEQ * HD, 2, 2);

    // 8. out[bs][m] = ctxv @ Wo^T    (M=4096,N=2048,K=2048)
    gemm_mma<<<dim3(D_MODEL / 128, BS / 128, 1), blk, SMEM_BYTES>>>(
        ctxv, Wo, out, HD, HD, HD, D_MODEL,
        0, 0, 1, 0, 1, 0, 0, 1, 0);
}

// round 10
// speedup vs baseline: 6.3422x; 1.0455x over previous
#include <cuda_runtime.h>
#include <cuda_bf16.h>
#include <math.h>
#include <stdint.h>

#define D_MODEL 2048
#define D_HEAD  128
#define NHEADS  16
#define CLAT    512
#define BATCH   2
#define SEQ     2048
#define BS      (BATCH*SEQ)   // 4096
#define HD      (NHEADS*D_HEAD)

typedef __nv_bfloat16 bf16;
typedef __nv_bfloat162 bf162;

// fp32 scratch
__device__ float g_v[(size_t)NHEADS * BS * D_HEAD];             //  32 MB [(h)][bs][128]
__device__ float g_scores[(size_t)NHEADS * BATCH * SEQ * SEQ];  // 512 MB [(2h+b)][s][t]
// bf16 hi/lo operand buffers
__device__ bf16 bx_h[(size_t)BS * D_MODEL],      bx_l[(size_t)BS * D_MODEL];
__device__ bf16 bWd_h[(size_t)CLAT * D_MODEL],   bWd_l[(size_t)CLAT * D_MODEL];
__device__ bf16 bWq_h[(size_t)HD * D_MODEL],     bWq_l[(size_t)HD * D_MODEL];
__device__ bf16 bWuk_h[(size_t)HD * CLAT],       bWuk_l[(size_t)HD * CLAT];
__device__ bf16 bWuv_h[(size_t)HD * CLAT],       bWuv_l[(size_t)HD * CLAT];
__device__ bf16 bWo_h[(size_t)D_MODEL * HD],     bWo_l[(size_t)D_MODEL * HD];
__device__ bf16 blat_h[(size_t)BS * CLAT],       blat_l[(size_t)BS * CLAT];
__device__ bf16 bqh_h[(size_t)BS * HD],          bqh_l[(size_t)BS * HD];
__device__ bf16 bk_h[(size_t)NHEADS * BS * D_HEAD], bk_l[(size_t)NHEADS * BS * D_HEAD];
__device__ bf16 bvT_h[(size_t)NHEADS * BS * D_HEAD], bvT_l[(size_t)NHEADS * BS * D_HEAD];
__device__ bf16 bP_h[(size_t)NHEADS * BATCH * SEQ * SEQ], bP_l[(size_t)NHEADS * BATCH * SEQ * SEQ];
__device__ bf16 bctx_h[(size_t)BS * HD],         bctx_l[(size_t)BS * HD];

// ---------------- primitives ----------------
__device__ __forceinline__ uint32_t smem_u32(const void* p) {
    uint32_t a;
    asm("{ .reg .u64 t; cvta.to.shared.u64 t, %1; cvt.u32.u64 %0, t; }" : "=r"(a) : "l"(p));
    return a;
}
__device__ __forceinline__ void ldsm_x4(uint32_t addr, uint32_t r[4]) {
    asm volatile("ldmatrix.sync.aligned.m8n8.x4.shared.b16 {%0,%1,%2,%3}, [%4];"
        : "=r"(r[0]), "=r"(r[1]), "=r"(r[2]), "=r"(r[3]) : "r"(addr));
}
__device__ __forceinline__ void mma16816(float c[4], const uint32_t a[4], const uint32_t b[2]) {
    asm volatile(
        "mma.sync.aligned.m16n8k16.row.col.f32.bf16.bf16.f32 "
        "{%0,%1,%2,%3}, {%4,%5,%6,%7}, {%8,%9}, {%0,%1,%2,%3};"
        : "+f"(c[0]), "+f"(c[1]), "+f"(c[2]), "+f"(c[3])
        : "r"(a[0]), "r"(a[1]), "r"(a[2]), "r"(a[3]), "r"(b[0]), "r"(b[1]));
}
#define CP16(dst, src) asm volatile("cp.async.cg.shared.global [%0], [%1], 16;" :: "r"(dst), "l"(src))
#define CP_COMMIT() asm volatile("cp.async.commit_group;" ::: "memory")
#define CP_WAIT1() asm volatile("cp.async.wait_group 1;" ::: "memory")
#define CP_WAIT0() asm volatile("cp.async.wait_group 0;" ::: "memory")

__device__ __forceinline__ bf162 split_hi(float a, float b, bf162& lo) {
    bf162 hi = __floats2bfloat162_rn(a, b);
    lo = __floats2bfloat162_rn(a - __bfloat162float(__low2bfloat16(hi)),
                               b - __bfloat162float(__high2bfloat16(hi)));
    return hi;
}

// SMEM tile: 128 rows x 32 k bf16, row stride 80 B
#define ROWB 80
#define TILEB (128 * ROWB)            // 10240
#define STAGEB (4 * TILEB)            // 40960 per stage (Ah Al Bh Bl)
#define SMEM_BYTES (2 * STAGEB + 128)

// ---------------- cp.async split-bf16 GEMM ----------------
// C[z][M,N] = A[z] @ B[z]^T ; A,B pre-split (hi,lo) bf16 row-major [m][k] / [n][k]
// OUTMODE 0: fp32 C ; OUTMODE 1: bf16 hi/lo pair C
template<int OUTMODE>
__global__ void __launch_bounds__(256, 2) gemm_pk(
    const bf16* __restrict__ Ah, const bf16* __restrict__ Al,
    const bf16* __restrict__ Bh, const bf16* __restrict__ Bl,
    float* __restrict__ C, bf16* __restrict__ Ch, bf16* __restrict__ Cl,
    int K, int lda, int ldb, int ldc,
    size_t sAz, size_t sAz2, int zAdiv,
    size_t sBz, int zBmod,
    size_t sCz, size_t sCz2, int zCdiv, int causalMode)
{
    int bn = blockIdx.x, bm = blockIdx.y, z = blockIdx.z;
    if (causalMode == 1 && bn > bm) return;
    int Kend = K;
    if (causalMode == 2) { int lim = (bm + 1) * 128; if (lim < Kend) Kend = lim; }

    size_t aoff = (size_t)(z / zAdiv) * sAz + (size_t)(z % zAdiv) * sAz2;
    size_t boff = (size_t)(z % zBmod) * sBz;
    size_t coff = (size_t)(z / zCdiv) * sCz + (size_t)(z % zCdiv) * sCz2;
    Ah += aoff; Al += aoff; Bh += boff; Bl += boff;

    extern __shared__ char smraw[];
    char* sm = (char*)(((uintptr_t)smraw + 127) & ~(uintptr_t)127);
    uint32_t sbase = smem_u32(sm);

    int tid = threadIdx.x;
    int wid = tid >> 5, lane = tid & 31;
    int m0 = bm * 128, n0 = bn * 128;

    // staging: thread t -> row t>>1, segs 2*(t&1), 2*(t&1)+1 (16B each)
    int srow = tid >> 1;
    int sseg = (tid & 1) * 2;
    const bf16* gA = Ah + (size_t)(m0 + srow) * lda + sseg * 8;
    const bf16* gAl = Al + (size_t)(m0 + srow) * lda + sseg * 8;
    const bf16* gB = Bh + (size_t)(n0 + srow) * ldb + sseg * 8;
    const bf16* gBl = Bl + (size_t)(n0 + srow) * ldb + sseg * 8;
    uint32_t dOff = (uint32_t)srow * ROWB + (uint32_t)sseg * 16;

    // warp tiling: 2x4 warps, warp tile 64x32
    int wm = wid & 1, wn = wid >> 1;
    uint32_t aRow = (uint32_t)(wm * 64 + (lane & 15));
    uint32_t aK8  = (uint32_t)((lane >> 4) * 8);
    uint32_t bRow = (uint32_t)(wn * 32 + (lane & 7) + ((lane >> 4) & 1) * 8);
    uint32_t bK8  = (uint32_t)(((lane >> 3) & 1) * 8);

    float acc[4][4][4];
#pragma unroll
    for (int i = 0; i < 4; i++)
#pragma unroll
        for (int j = 0; j < 4; j++)
#pragma unroll
            for (int r = 0; r < 4; r++) acc[i][j][r] = 0.f;

    int ncha = Kend / 32;

#define STAGE(k0, soffst) do { \
    uint32_t d_ = sbase + (soffst) + dOff; \
    CP16(d_,              gA  + (k0));      CP16(d_ + 16,              gA  + (k0) + 8); \
    CP16(d_ + TILEB,      gAl + (k0));      CP16(d_ + TILEB + 16,      gAl + (k0) + 8); \
    CP16(d_ + 2*TILEB,    gB  + (k0));      CP16(d_ + 2*TILEB + 16,    gB  + (k0) + 8); \
    CP16(d_ + 3*TILEB,    gBl + (k0));      CP16(d_ + 3*TILEB + 16,    gBl + (k0) + 8); \
} while (0)

    // prologue
    STAGE(0, 0); CP_COMMIT();
    if (ncha > 1) { STAGE(32, STAGEB); CP_COMMIT(); CP_WAIT1(); }
    else CP_WAIT0();
    __syncthreads();

    for (int c = 0; c < ncha; c++) {
        uint32_t sb = sbase + (uint32_t)(c & 1) * STAGEB;
        uint32_t sbAh = sb, sbAl = sb + TILEB, sbBh = sb + 2 * TILEB, sbBl = sb + 3 * TILEB;
#pragma unroll
        for (int ks = 0; ks < 2; ks++) {
            uint32_t k0 = (uint32_t)(ks * 16);
            uint32_t Afh[4][4], Afl[4][4], Bfh[2][4], Bfl[2][4];
#pragma unroll
            for (int im = 0; im < 4; im++) {
                uint32_t ao = (aRow + im * 16) * ROWB + (k0 + aK8) * 2;
                ldsm_x4(sbAh + ao, Afh[im]);
                ldsm_x4(sbAl + ao, Afl[im]);
            }
#pragma unroll
            for (int p = 0; p < 2; p++) {
                uint32_t bo = (bRow + p * 16) * ROWB + (k0 + bK8) * 2;
                ldsm_x4(sbBh + bo, Bfh[p]);
                ldsm_x4(sbBl + bo, Bfl[p]);
            }
#pragma unroll
            for (int im = 0; im < 4; im++)
#pragma unroll
                for (int in_ = 0; in_ < 4; in_++) {
                    int p = in_ >> 1, q = (in_ & 1) * 2;
                    mma16816(acc[im][in_], Afh[im], &Bfh[p][q]);
                    mma16816(acc[im][in_], Afh[im], &Bfl[p][q]);
                    mma16816(acc[im][in_], Afl[im], &Bfh[p][q]);
                }
        }
        __syncthreads();   // everyone done reading buf (c&1)
        if (c + 2 < ncha) {
            STAGE((c + 2) * 32, (uint32_t)(c & 1) * STAGEB); CP_COMMIT();
            CP_WAIT1(); __syncthreads();
        } else if (c + 1 < ncha) {
            CP_WAIT0(); __syncthreads();
        }
    }
#undef STAGE

    // epilogue
#pragma unroll
    for (int im = 0; im < 4; im++) {
        int r0 = m0 + wm * 64 + im * 16 + (lane >> 2);
#pragma unroll
        for (int in_ = 0; in_ < 4; in_++) {
            int c0 = n0 + wn * 32 + in_ * 8 + (lane & 3) * 2;
            if (OUTMODE == 0) {
                *(float2*)&C[coff + (size_t)r0 * ldc + c0] =
                    make_float2(acc[im][in_][0], acc[im][in_][1]);
                *(float2*)&C[coff + (size_t)(r0 + 8) * ldc + c0] =
                    make_float2(acc[im][in_][2], acc[im][in_][3]);
            } else {
                bf162 lo0, lo1;
                bf162 hi0 = split_hi(acc[im][in_][0], acc[im][in_][1], lo0);
                bf162 hi1 = split_hi(acc[im][in_][2], acc[im][in_][3], lo1);
                size_t i0 = coff + (size_t)r0 * ldc + c0;
                size_t i1 = coff + (size_t)(r0 + 8) * ldc + c0;
                *(bf162*)&Ch[i0] = hi0; *(bf162*)&Cl[i0] = lo0;
                *(bf162*)&Ch[i1] = hi1; *(bf162*)&Cl[i1] = lo1;
            }
        }
    }
}

// ---------------- fp32 -> (hi,lo) bf16 convert ----------------
__global__ __launch_bounds__(256) void cvt_split_k(
    const float* __restrict__ in, bf16* __restrict__ h, bf16* __restrict__ l, int n4)
{
    int i = blockIdx.x * 256 + threadIdx.x;
    if (i >= n4) return;
    float4 v = *(const float4*)(in + (size_t)i * 4);
    bf162 l0, l1;
    bf162 h0 = split_hi(v.x, v.y, l0);
    bf162 h1 = split_hi(v.z, v.w, l1);
    *(bf162*)&h[(size_t)i * 4]     = h0;
    *(bf162*)&h[(size_t)i * 4 + 2] = h1;
    *(bf162*)&l[(size_t)i * 4]     = l0;
    *(bf162*)&l[(size_t)i * 4 + 2] = l1;
}

// ---------------- transpose + split: fp32 [t][d] -> bf16 pair [d][t] ------
// REQUIRES block = dim3(32, 8)
__global__ void transpose_split_k(
    const float* __restrict__ in, bf16* __restrict__ oh, bf16* __restrict__ ol,
    int R, int C, size_t inz, size_t outz)
{
    __shared__ float t[32][33];
    const float* pi = in + (size_t)blockIdx.z * inz;
    int c = blockIdx.x * 32 + threadIdx.x;
    int r0 = blockIdx.y * 32 + threadIdx.y;
#pragma unroll
    for (int i = 0; i < 32; i += 8)
        t[threadIdx.y + i][threadIdx.x] = pi[(size_t)(r0 + i) * C + c];
    __syncthreads();
    int rc = blockIdx.y * 32 + threadIdx.x;
    int cr0 = blockIdx.x * 32 + threadIdx.y;
#pragma unroll
    for (int i = 0; i < 32; i += 8) {
        float v = t[threadIdx.x][threadIdx.y + i];
        bf16 hh = __float2bfloat16(v);
        size_t idx = (size_t)blockIdx.z * outz + (size_t)(cr0 + i) * R + rc;
        oh[idx] = hh;
        ol[idx] = __float2bfloat16(v - __bfloat162float(hh));
    }
}

// ---------------- causal softmax: fp32 in, bf16 hi/lo out ----------------
__global__ __launch_bounds__(256) void softmax_causal_k(
    const float* __restrict__ scores, bf16* __restrict__ ph, bf16* __restrict__ pl,
    float scale)
{
    __shared__ float srow[SEQ];
    __shared__ float red[256];
    int r = blockIdx.x;
    int z = r >> 11;
    int s = r & (SEQ - 1);
    const float* p = scores + ((size_t)z * SEQ + (size_t)s) * SEQ;
    size_t obase = ((size_t)z * SEQ + (size_t)s) * SEQ;
    int n = s + 1;
    int tid = threadIdx.x;

    float m = -3.0e38f;
    for (int j = tid; j < n; j += 256) { float vv = p[j]; srow[j] = vv; m = fmaxf(m, vv); }
    red[tid] = m; __syncthreads();
    for (int o = 128; o > 0; o >>= 1) { if (tid < o) red[tid] = fmaxf(red[tid], red[tid + o]); __syncthreads(); }
    m = red[0]; __syncthreads();

    float sum = 0.f;
    for (int j = tid; j < n; j += 256) {
        float e = expf((srow[j] - m) * scale);
        srow[j] = e;
        sum += e;
    }
    red[tid] = sum; __syncthreads();
    for (int o = 128; o > 0; o >>= 1) { if (tid < o) red[tid] += red[tid + o]; __syncthreads(); }
    float inv = 1.f / red[0];

    for (int j = tid; j < n; j += 256) {
        float v = srow[j] * inv;
        bf16 hh = __float2bfloat16(v);
        ph[obase + j] = hh;
        pl[obase + j] = __float2bfloat16(v - __bfloat162float(hh));
    }
    int zend = ((s >> 7) + 1) << 7;     // ctx truncates K at this boundary
    bf16 z0 = __float2bfloat16(0.f);
    for (int j = n + tid; j < zend; j += 256) { ph[obase + j] = z0; pl[obase + j] = z0; }
}

template<typename T>
static T* symaddr(const void* sym) {
    void* p = nullptr;
    cudaGetSymbolAddress(&p, sym);
    return (T*)p;
}

extern "C" void kernel_launch(void* const* d_in, const int* in_sizes, int n_in,
                              void* d_out, int out_size)
{
    const float* x   = (const float*)d_in[0];
    const float* Wd  = (const float*)d_in[1];
    const float* Wuk = (const float*)d_in[2];
    const float* Wuv = (const float*)d_in[3];
    const float* Wq  = (const float*)d_in[4];
    const float* Wo  = (const float*)d_in[5];
    float* out = (float*)d_out;

    float* vbuf   = symaddr<float>(g_v);
    float* scores = symaddr<float>(g_scores);
    bf16 *xh = symaddr<bf16>(bx_h),   *xl = symaddr<bf16>(bx_l);
    bf16 *wdh = symaddr<bf16>(bWd_h), *wdl = symaddr<bf16>(bWd_l);
    bf16 *wqh = symaddr<bf16>(bWq_h), *wql = symaddr<bf16>(bWq_l);
    bf16 *wukh = symaddr<bf16>(bWuk_h), *wukl = symaddr<bf16>(bWuk_l);
    bf16 *wuvh = symaddr<bf16>(bWuv_h), *wuvl = symaddr<bf16>(bWuv_l);
    bf16 *woh = symaddr<bf16>(bWo_h), *wol = symaddr<bf16>(bWo_l);
    bf16 *lath = symaddr<bf16>(blat_h), *latl = symaddr<bf16>(blat_l);
    bf16 *qhh = symaddr<bf16>(bqh_h), *qhl = symaddr<bf16>(bqh_l);
    bf16 *kh = symaddr<bf16>(bk_h),   *kl = symaddr<bf16>(bk_l);
    bf16 *vth = symaddr<bf16>(bvT_h), *vtl = symaddr<bf16>(bvT_l);
    bf16 *pph = symaddr<bf16>(bP_h),  *ppl = symaddr<bf16>(bP_l);
    bf16 *cth = symaddr<bf16>(bctx_h), *ctl = symaddr<bf16>(bctx_l);

    cudaFuncSetAttribute(gemm_pk<0>, cudaFuncAttributeMaxDynamicSharedMemorySize, SMEM_BYTES);
    cudaFuncSetAttribute(gemm_pk<1>, cudaFuncAttributeMaxDynamicSharedMemorySize, SMEM_BYTES);

    dim3 blk(256);
    dim3 tblk(32, 8);
    const size_t SS  = (size_t)SEQ * SEQ;
    const size_t SD  = (size_t)SEQ * D_HEAD;
    const size_t BSD = (size_t)BS * D_HEAD;

    // 0. convert inputs to (hi,lo) bf16
    cvt_split_k<<<(BS * D_MODEL / 4 + 255) / 256, blk>>>(x, xh, xl, BS * D_MODEL / 4);
    cvt_split_k<<<(CLAT * D_MODEL / 4 + 255) / 256, blk>>>(Wd, wdh, wdl, CLAT * D_MODEL / 4);
    cvt_split_k<<<(HD * D_MODEL / 4 + 255) / 256, blk>>>(Wq, wqh, wql, HD * D_MODEL / 4);
    cvt_split_k<<<(HD * CLAT / 4 + 255) / 256, blk>>>(Wuk, wukh, wukl, HD * CLAT / 4);
    cvt_split_k<<<(HD * CLAT / 4 + 255) / 256, blk>>>(Wuv, wuvh, wuvl, HD * CLAT / 4);
    cvt_split_k<<<(D_MODEL * HD / 4 + 255) / 256, blk>>>(Wo, woh, wol, D_MODEL * HD / 4);

    // 1. latents = x @ Wd^T  -> bf16 pair  (M=4096,N=512,K=2048)
    gemm_pk<1><<<dim3(CLAT / 128, BS / 128, 1), blk, SMEM_BYTES>>>(
        xh, xl, wdh, wdl, nullptr, lath, latl,
        D_MODEL, D_MODEL, D_MODEL, CLAT,
        0, 0, 1, 0, 1, 0, 0, 1, 0);

    // 2. qh = x @ Wq^T  -> bf16 pair  (M=4096,N=2048,K=2048)
    gemm_pk<1><<<dim3(HD / 128, BS / 128, 1), blk, SMEM_BYTES>>>(
        xh, xl, wqh, wql, nullptr, qhh, qhl,
        D_MODEL, D_MODEL, D_MODEL, HD,
        0, 0, 1, 0, 1, 0, 0, 1, 0);

    // 3. k[h] = latents @ Wuk_h^T -> bf16 pair  (M=4096,N=128,K=512)
    gemm_pk<1><<<dim3(1, BS / 128, NHEADS), blk, SMEM_BYTES>>>(
        lath, latl, wukh, wukl, nullptr, kh, kl,
        CLAT, CLAT, CLAT, D_HEAD,
        0, 0, 1, (size_t)D_HEAD * CLAT, NHEADS, BSD, 0, 1, 0);

    // 4. v[h] = latents @ Wuv_h^T -> fp32 (for transpose)
    gemm_pk<0><<<dim3(1, BS / 128, NHEADS), blk, SMEM_BYTES>>>(
        lath, latl, wuvh, wuvl, vbuf, nullptr, nullptr,
        CLAT, CLAT, CLAT, D_HEAD,
        0, 0, 1, (size_t)D_HEAD * CLAT, NHEADS, BSD, 0, 1, 0);

    // 4b. vT[(2h+b)][d][t] = v^T  -> bf16 pair
    transpose_split_k<<<dim3(D_HEAD / 32, SEQ / 32, NHEADS * BATCH), tblk>>>(
        vbuf, vth, vtl, SEQ, D_HEAD, SD, SD);

    // 5. scores = qh_slice @ k_hb^T -> fp32  (M=N=2048,K=128, causal skip)
    gemm_pk<0><<<dim3(SEQ / 128, SEQ / 128, NHEADS * BATCH), blk, SMEM_BYTES>>>(
        qhh, qhl, kh, kl, scores, nullptr, nullptr,
        D_HEAD, HD, D_HEAD, SEQ,
        (size_t)D_HEAD, (size_t)SEQ * HD, 2,
        SD, NHEADS * BATCH, SS, 0, 1, 1);

    // 6. softmax -> P bf16 pair (+ zero-fill to 128 boundary)
    softmax_causal_k<<<NHEADS * BATCH * SEQ, blk>>>(scores, pph, ppl, 0.08838834764831845f);

    // 7. ctx = P @ vT^T -> bf16 pair  (M=2048,N=128,K trunc)
    gemm_pk<1><<<dim3(1, SEQ / 128, NHEADS * BATCH), blk, SMEM_BYTES>>>(
        pph, ppl, vth, vtl, nullptr, cth, ctl,
        SEQ, SEQ, SEQ, HD,
        SS, 0, 1, SD, NHEADS * BATCH,
        (size_t)D_HEAD, (size_t)SEQ * HD, 2, 2);

    // 8. out = ctx @ Wo^T -> fp32  (M=4096,N=2048,K=2048)
    gemm_pk<0><<<dim3(D_MODEL / 128, BS / 128, 1), blk, SMEM_BYTES>>>(
        cth, ctl, woh, wol, out, nullptr, nullptr,
        HD, HD, HD, D_MODEL,
        0, 0, 1, 0, 1, 0, 0, 1, 0);
}